// round 14
// baseline (speedup 1.0000x reference)
#include <cuda_runtime.h>

// infer/ref shape (2,7,7,3,256,256) -> N=98 images, C=3, H=W=256
#define NIMG   98
#define HH     256
#define WW     256
#define WSTRIP 4                             // rows per WARP
#define BSTRIP 16                            // rows per BLOCK (4 warps)
#define NBLK_PER_IMG (HH / BSTRIP)           // 16
#define NBLOCKS (NIMG * NBLK_PER_IMG)        // 1568
#define CH_STRIDE (HH * WW)                  // 65536 floats per channel
#define IMG_STRIDE (3 * CH_STRIDE)
#define CS4 (CH_STRIDE / 4)                  // 16384 float4 per channel
#define W4  (WW / 4)                         // 64 float4 per row

__device__ float g_partials[NBLOCKS];
__device__ unsigned int g_count;             // zero-init; self-resets each run

// Coalesced row load: lane owns float4 columns {lane, lane+32}.
// d0 = D[gh][4*lane .. 4*lane+3], d1 = D[gh][128+4*lane ..], D = sum_c(infer-ref).
// Zeros for out-of-image rows. Every LDG.128 is warp-contiguous (512 B).
static __device__ __forceinline__ void load_row(
    const float4* __restrict__ A, const float4* __restrict__ B,
    int gh, int lane, float4& d0, float4& d1)
{
    d0 = make_float4(0.f, 0.f, 0.f, 0.f);
    d1 = make_float4(0.f, 0.f, 0.f, 0.f);
    if ((unsigned)gh < (unsigned)HH) {
        const int o0 = gh * W4 + lane;       // first half of the row
        const int o1 = o0 + 32;              // second half
        float4 a0 = A[o0];             float4 b0 = B[o0];
        float4 a1 = A[o0 + CS4];       float4 b1 = B[o0 + CS4];
        float4 a2 = A[o0 + 2*CS4];     float4 b2 = B[o0 + 2*CS4];
        float4 c0 = A[o1];             float4 e0 = B[o1];
        float4 c1 = A[o1 + CS4];       float4 e1 = B[o1 + CS4];
        float4 c2 = A[o1 + 2*CS4];     float4 e2 = B[o1 + 2*CS4];
        d0.x = (a0.x-b0.x)+(a1.x-b1.x)+(a2.x-b2.x);
        d0.y = (a0.y-b0.y)+(a1.y-b1.y)+(a2.y-b2.y);
        d0.z = (a0.z-b0.z)+(a1.z-b1.z)+(a2.z-b2.z);
        d0.w = (a0.w-b0.w)+(a1.w-b1.w)+(a2.w-b2.w);
        d1.x = (c0.x-e0.x)+(c1.x-e1.x)+(c2.x-e2.x);
        d1.y = (c0.y-e0.y)+(c1.y-e1.y)+(c2.y-e2.y);
        d1.z = (c0.z-e0.z)+(c1.z-e1.z)+(c2.z-e2.z);
        d1.w = (c0.w-e0.w)+(c1.w-e1.w)+(c2.w-e2.w);
    }
}

// Horizontal term |d[w+1] - d[w-1]| (zero-padded in w) for one row.
static __device__ __forceinline__ float horiz_row(
    int lane, const float4& d0, const float4& d1)
{
    float l0 = __shfl_up_sync(0xffffffffu, d0.w, 1);       // col 4j-1
    if (lane == 0) l0 = 0.f;                               // col -1 pad
    float r0 = __shfl_down_sync(0xffffffffu, d0.x, 1);     // col 4j+4
    float seamR = __shfl_sync(0xffffffffu, d1.x, 0);       // col 128 (lane 31)
    if (lane == 31) r0 = seamR;
    float l1 = __shfl_up_sync(0xffffffffu, d1.w, 1);
    float seamL = __shfl_sync(0xffffffffu, d0.w, 31);      // col 127 (lane 0)
    if (lane == 0) l1 = seamL;
    float r1 = __shfl_down_sync(0xffffffffu, d1.x, 1);
    if (lane == 31) r1 = 0.f;                              // col 256 pad

    return fabsf(d0.y - l0)   + fabsf(d0.z - d0.x)
         + fabsf(d0.w - d0.y) + fabsf(r0   - d0.z)
         + fabsf(d1.y - l1)   + fabsf(d1.z - d1.x)
         + fabsf(d1.w - d1.y) + fabsf(r1   - d1.z);
}

static __device__ __forceinline__ float vert_pair(
    const float4& n0, const float4& n1, const float4& p0, const float4& p1)
{
    return fabsf(n0.x - p0.x) + fabsf(n0.y - p0.y)
         + fabsf(n0.z - p0.z) + fabsf(n0.w - p0.w)
         + fabsf(n1.x - p1.x) + fabsf(n1.y - p1.y)
         + fabsf(n1.z - p1.z) + fabsf(n1.w - p1.w);
}

__global__ __launch_bounds__(128)
void detail_loss_stream(const float* __restrict__ infer,
                        const float* __restrict__ ref,
                        float* __restrict__ out)
{
    __shared__ float wsum[4];
    __shared__ int   s_last;

    const int tid  = threadIdx.x;
    const int lane = tid & 31;
    const int wid  = tid >> 5;               // 0..3
    const int blk  = blockIdx.x;
    const int n    = blk >> 4;               // image
    const int t    = blk & 15;               // 16-row block strip
    const int h0   = t * BSTRIP + wid * WSTRIP;  // this warp's first row

    const size_t base = (size_t)n * IMG_STRIDE;
    const float4* __restrict__ A = (const float4*)(infer + base);
    const float4* __restrict__ B = (const float4*)(ref   + base);

    // Rolling window: p = D[i-1], c = D[i], load n = D[i+1] per step.
    float4 p0, p1, c0, c1, n0, n1;
    load_row(A, B, h0 - 1, lane, p0, p1);    // halo above (zeros at image top)
    load_row(A, B, h0,     lane, c0, c1);

    float acc = 0.f;
    #pragma unroll
    for (int i = 0; i < WSTRIP; i++) {
        load_row(A, B, h0 + 1 + i, lane, n0, n1);        // D[i+1]
        acc += horiz_row(lane, c0, c1) + vert_pair(n0, n1, p0, p1);
        p0 = c0; p1 = c1; c0 = n0; c1 = n1;
    }

    // warp reduction (fixed order -> deterministic)
    #pragma unroll
    for (int o = 16; o > 0; o >>= 1)
        acc += __shfl_xor_sync(0xffffffffu, acc, o);
    if (lane == 0) wsum[wid] = acc;
    __syncthreads();

    // block reduce (fixed order) + partial store
    if (tid == 0) {
        float b = (wsum[0] + wsum[1]) + (wsum[2] + wsum[3]);
        g_partials[blk] = b;
        __threadfence();
        unsigned old = atomicAdd(&g_count, 1u);
        s_last = (old == NBLOCKS - 1);
        if (s_last) g_count = 0;             // reset for next graph replay
    }
    __syncthreads();

    // fused final reduction: last-finishing block sums all partials
    if (s_last && wid == 0) {
        __threadfence();                      // acquire all partials
        float s = 0.f;
        for (int i = lane; i < NBLOCKS; i += 32) s += g_partials[i];
        #pragma unroll
        for (int o = 16; o > 0; o >>= 1)
            s += __shfl_xor_sync(0xffffffffu, s, o);
        if (lane == 0) {
            // result = A / (4 * 98 * 258 * 256): 0.5 grad coeff folded out,
            // /2 average of the two losses, mean denom 98*258*256 per term.
            out[0] = s * (1.0f / 25890816.0f);
        }
    }
}

extern "C" void kernel_launch(void* const* d_in, const int* in_sizes, int n_in,
                              void* d_out, int out_size)
{
    const float* infer = (const float*)d_in[0];
    const float* ref   = (const float*)d_in[1];
    float* out = (float*)d_out;
    (void)in_sizes; (void)n_in; (void)out_size;

    detail_loss_stream<<<NBLOCKS, 128>>>(infer, ref, out);
}

// round 15
// speedup vs baseline: 1.1189x; 1.1189x over previous
#include <cuda_runtime.h>

// infer/ref shape (2,7,7,3,256,256) -> N=98 images, C=3, H=W=256
#define NIMG   98
#define HH     256
#define WW     256
#define WSTRIP 8                             // rows per WARP
#define BSTRIP 32                            // rows per BLOCK (4 warps)
#define NBLK_PER_IMG (HH / BSTRIP)           // 8
#define NBLOCKS (NIMG * NBLK_PER_IMG)        // 784
#define CH_STRIDE (HH * WW)                  // 65536 floats per channel
#define IMG_STRIDE (3 * CH_STRIDE)
#define CS4 (CH_STRIDE / 4)                  // 16384 float4 per channel
#define W4  (WW / 4)                         // 64 float4 per row

__device__ float g_partials[NBLOCKS];
__device__ unsigned int g_count;             // zero-init; self-resets each run

// Coalesced row load: lane owns float4 columns {lane, lane+32}.
// d0 = D[gh][4*lane .. 4*lane+3], d1 = D[gh][128+4*lane ..], D = sum_c(infer-ref).
// Zeros for out-of-image rows. Every LDG.128 is warp-contiguous (512 B).
static __device__ __forceinline__ void load_row(
    const float4* __restrict__ A, const float4* __restrict__ B,
    int gh, int lane, float4& d0, float4& d1)
{
    d0 = make_float4(0.f, 0.f, 0.f, 0.f);
    d1 = make_float4(0.f, 0.f, 0.f, 0.f);
    if ((unsigned)gh < (unsigned)HH) {
        const int o0 = gh * W4 + lane;       // first half of the row
        const int o1 = o0 + 32;              // second half
        float4 a0 = A[o0];             float4 b0 = B[o0];
        float4 a1 = A[o0 + CS4];       float4 b1 = B[o0 + CS4];
        float4 a2 = A[o0 + 2*CS4];     float4 b2 = B[o0 + 2*CS4];
        float4 c0 = A[o1];             float4 e0 = B[o1];
        float4 c1 = A[o1 + CS4];       float4 e1 = B[o1 + CS4];
        float4 c2 = A[o1 + 2*CS4];     float4 e2 = B[o1 + 2*CS4];
        d0.x = (a0.x-b0.x)+(a1.x-b1.x)+(a2.x-b2.x);
        d0.y = (a0.y-b0.y)+(a1.y-b1.y)+(a2.y-b2.y);
        d0.z = (a0.z-b0.z)+(a1.z-b1.z)+(a2.z-b2.z);
        d0.w = (a0.w-b0.w)+(a1.w-b1.w)+(a2.w-b2.w);
        d1.x = (c0.x-e0.x)+(c1.x-e1.x)+(c2.x-e2.x);
        d1.y = (c0.y-e0.y)+(c1.y-e1.y)+(c2.y-e2.y);
        d1.z = (c0.z-e0.z)+(c1.z-e1.z)+(c2.z-e2.z);
        d1.w = (c0.w-e0.w)+(c1.w-e1.w)+(c2.w-e2.w);
    }
}

// Horizontal term |d[w+1] - d[w-1]| (zero-padded in w) for one row.
static __device__ __forceinline__ float horiz_row(
    int lane, const float4& d0, const float4& d1)
{
    float l0 = __shfl_up_sync(0xffffffffu, d0.w, 1);       // col 4j-1
    if (lane == 0) l0 = 0.f;                               // col -1 pad
    float r0 = __shfl_down_sync(0xffffffffu, d0.x, 1);     // col 4j+4
    float seamR = __shfl_sync(0xffffffffu, d1.x, 0);       // col 128 (lane 31)
    if (lane == 31) r0 = seamR;
    float l1 = __shfl_up_sync(0xffffffffu, d1.w, 1);
    float seamL = __shfl_sync(0xffffffffu, d0.w, 31);      // col 127 (lane 0)
    if (lane == 0) l1 = seamL;
    float r1 = __shfl_down_sync(0xffffffffu, d1.x, 1);
    if (lane == 31) r1 = 0.f;                              // col 256 pad

    return fabsf(d0.y - l0)   + fabsf(d0.z - d0.x)
         + fabsf(d0.w - d0.y) + fabsf(r0   - d0.z)
         + fabsf(d1.y - l1)   + fabsf(d1.z - d1.x)
         + fabsf(d1.w - d1.y) + fabsf(r1   - d1.z);
}

static __device__ __forceinline__ float vert_pair(
    const float4& n0, const float4& n1, const float4& p0, const float4& p1)
{
    return fabsf(n0.x - p0.x) + fabsf(n0.y - p0.y)
         + fabsf(n0.z - p0.z) + fabsf(n0.w - p0.w)
         + fabsf(n1.x - p1.x) + fabsf(n1.y - p1.y)
         + fabsf(n1.z - p1.z) + fabsf(n1.w - p1.w);
}

__global__ __launch_bounds__(128)
void detail_loss_stream(const float* __restrict__ infer,
                        const float* __restrict__ ref,
                        float* __restrict__ out)
{
    __shared__ float wsum[4];
    __shared__ float fsum[4];
    __shared__ int   s_last;

    const int tid  = threadIdx.x;
    const int lane = tid & 31;
    const int wid  = tid >> 5;               // 0..3
    const int blk  = blockIdx.x;
    const int n    = blk >> 3;               // image
    const int t    = blk & 7;                // 32-row block strip
    const int h0   = t * BSTRIP + wid * WSTRIP;  // this warp's first row

    const size_t base = (size_t)n * IMG_STRIDE;
    const float4* __restrict__ A = (const float4*)(infer + base);
    const float4* __restrict__ B = (const float4*)(ref   + base);

    // Rolling window: p = D[i-1], c = D[i], load n = D[i+1] per step.
    float4 p0, p1, c0, c1, n0, n1;
    load_row(A, B, h0 - 1, lane, p0, p1);    // halo above (zeros at image top)
    load_row(A, B, h0,     lane, c0, c1);

    float acc = 0.f;
    #pragma unroll
    for (int i = 0; i < WSTRIP; i++) {
        load_row(A, B, h0 + 1 + i, lane, n0, n1);        // D[i+1]
        acc += horiz_row(lane, c0, c1) + vert_pair(n0, n1, p0, p1);
        p0 = c0; p1 = c1; c0 = n0; c1 = n1;
    }

    // warp reduction (fixed order -> deterministic)
    #pragma unroll
    for (int o = 16; o > 0; o >>= 1)
        acc += __shfl_xor_sync(0xffffffffu, acc, o);
    if (lane == 0) wsum[wid] = acc;
    __syncthreads();

    // block reduce (fixed order) + partial store + arrival counter
    if (tid == 0) {
        float b = (wsum[0] + wsum[1]) + (wsum[2] + wsum[3]);
        g_partials[blk] = b;
        __threadfence();
        unsigned old = atomicAdd(&g_count, 1u);
        s_last = (old == NBLOCKS - 1);
        if (s_last) g_count = 0;             // reset for next graph replay
    }
    __syncthreads();

    // fused final reduction: last-finishing block sums all partials with
    // all 4 warps (784/4 = 196 per warp), fixed order -> deterministic.
    if (s_last) {
        __threadfence();                      // acquire all partials
        float s = 0.f;
        for (int i = wid * (NBLOCKS / 4) + lane; i < (wid + 1) * (NBLOCKS / 4); i += 32)
            s += g_partials[i];
        #pragma unroll
        for (int o = 16; o > 0; o >>= 1)
            s += __shfl_xor_sync(0xffffffffu, s, o);
        if (lane == 0) fsum[wid] = s;
        __syncthreads();
        if (tid == 0) {
            float tot = (fsum[0] + fsum[1]) + (fsum[2] + fsum[3]);
            // result = A / (4 * 98 * 258 * 256): 0.5 grad coeff folded out,
            // /2 average of the two losses, mean denom 98*258*256 per term.
            out[0] = tot * (1.0f / 25890816.0f);
        }
    }
}

extern "C" void kernel_launch(void* const* d_in, const int* in_sizes, int n_in,
                              void* d_out, int out_size)
{
    const float* infer = (const float*)d_in[0];
    const float* ref   = (const float*)d_in[1];
    float* out = (float*)d_out;
    (void)in_sizes; (void)n_in; (void)out_size;

    detail_loss_stream<<<NBLOCKS, 128>>>(infer, ref, out);
}